// round 7
// baseline (speedup 1.0000x reference)
#include <cuda_runtime.h>
#include <math.h>

#define N_IMG   64
#define C_PRED  85
#define HDIM    32
#define HW      1024
#define NCLS    80
#define CONF_TH 0.25f
#define NMS_TH  0.35f
#define MAXK    64

// Output layout (float32): [ bboxes: N*HW*6 ][ keep: N*HW ]
#define BBOX_ELEMS ((size_t)N_IMG * HW * 6)

// Dynamic shared memory layout (bytes)
#define OFF_SBOX   0                    // float4[1024]            16384
#define OFF_SKEY   16384                // u64[80*64]              40960
#define OFF_SRT    57344                // u64[32*32]               8192
#define OFF_MSM    65536                // u32[32*32]               4096
#define OFF_CCNT   69632                // int[80]                   320
#define OFF_SKEEP  69952                // u8[1024]                 1024
#define SMEM_TOTAL 70976

__global__ __launch_bounds__(1024, 1)
void fastestdet_fused_kernel(const float* __restrict__ preds,
                             float* __restrict__ out)
{
    extern __shared__ unsigned char smem_raw[];
    float4*             sbox   = (float4*)(smem_raw + OFF_SBOX);
    unsigned long long* skey   = (unsigned long long*)(smem_raw + OFF_SKEY);
    unsigned long long* srt    = (unsigned long long*)(smem_raw + OFF_SRT);
    unsigned*           Msm    = (unsigned*)(smem_raw + OFF_MSM);
    int*                ccount = (int*)(smem_raw + OFF_CCNT);
    unsigned char*      skeep  = (unsigned char*)(smem_raw + OFF_SKEEP);

    const int n = blockIdx.x;     // image
    const int t = threadIdx.x;    // cell 0..1023
    const int warpId = t >> 5;
    const int lane   = t & 31;

    if (t < NCLS) ccount[t] = 0;
    skeep[t] = 0;

    // ---------------- Phase 1: decode ----------------
    const float* p = preds + (size_t)n * C_PRED * HW + t;

    const float pobj = p[0];
    const float r0 = p[1 * HW];
    const float r1 = p[2 * HW];
    const float r2 = p[3 * HW];
    const float r3 = p[4 * HW];

    float mx = p[5 * HW];
    int   am = 0;
    #pragma unroll 8
    for (int c = 1; c < NCLS; ++c) {
        float v = p[(5 + c) * HW];
        if (v > mx) { mx = v; am = c; }   // strict '>' => first max index (jnp.argmax)
    }
    const float score = pobj * mx;

    const int w = t & (HDIM - 1);
    const int h = t >> 5;

    const float bw  = 1.0f / (1.0f + expf(-r2));
    const float bh  = 1.0f / (1.0f + expf(-r3));
    const float bcx = (tanhf(r0) + (float)w) * (1.0f / 32.0f);  // /32 exact
    const float bcy = (tanhf(r1) + (float)h) * (1.0f / 32.0f);

    const float x1 = bcx - 0.5f * bw;
    const float y1 = bcy - 0.5f * bh;
    const float x2 = bcx + 0.5f * bw;
    const float y2 = bcy + 0.5f * bh;

    float* ob = out + ((size_t)n * HW + t) * 6;
    ob[0] = x1; ob[1] = y1; ob[2] = x2; ob[3] = y2;
    ob[4] = score; ob[5] = (float)am;

    sbox[t] = make_float4(x1, y1, x2, y2);

    // ---------------- Phase 2: bucket by class ----------------
    if (score > CONF_TH) {
        const int slot = atomicAdd(&ccount[am], 1);
        if (slot < MAXK) {
            const unsigned long long kb = (unsigned long long)__float_as_uint(score);
            skey[am * MAXK + slot] = (kb << 10) | (unsigned long long)(HW - 1 - t);
        }
    }
    __syncthreads();

    // ---------------- Phase 3: per-class matrix greedy NMS ----------------
    // warp w handles classes w, w+32, w+64
    for (int c = warpId; c < NCLS; c += 32) {
        int k = ccount[c];
        if (k > MAXK) k = MAXK;
        if (k == 0) continue;

        if (k <= 32) {
            // load my key, compute rank = #{keys strictly greater} (stable argsort(-score))
            unsigned long long key = 0;
            if (lane < k) key = skey[c * MAXK + lane];
            int rank = 0;
            for (int j = 0; j < k; ++j) {
                const unsigned long long kj = skey[c * MAXK + j];  // broadcast LDS
                if (lane < k && kj > key) ++rank;
            }
            // permute so lane == rank
            if (lane < k) srt[warpId * 32 + rank] = key;
            __syncwarp();

            int    bi = 0;
            float4 cb = make_float4(0.f, 0.f, 0.f, 0.f);
            float  area = 0.f;
            if (lane < k) {
                const unsigned long long kr = srt[warpId * 32 + lane];
                bi   = (HW - 1) - (int)(kr & (HW - 1));
                cb   = sbox[bi];
                area = (cb.z - cb.x) * (cb.w - cb.y);
            }

            // suppression row: bit j set if IoU(me, box_j) > th (symmetric)
            unsigned M = 0;
            if (lane < k) {
                for (int j = 0; j < k; ++j) {
                    const unsigned long long kj = srt[warpId * 32 + j];
                    const int bj = (HW - 1) - (int)(kj & (HW - 1));
                    const float4 kb = sbox[bj];                    // broadcast LDS128
                    float iw = fminf(cb.z, kb.z) - fmaxf(cb.x, kb.x);
                    iw = fmaxf(iw, 0.0f);
                    float ih = fminf(cb.w, kb.w) - fmaxf(cb.y, kb.y);
                    ih = fmaxf(ih, 0.0f);
                    const float inter = iw * ih;
                    const float kba = (kb.z - kb.x) * (kb.w - kb.y);
                    const float iou = inter / (area + kba - inter + 1e-9f);
                    if (iou > NMS_TH) M |= (1u << j);
                }
                Msm[warpId * 32 + lane] = M;
            }
            __syncwarp();

            // uniform scalar greedy: self-bit in M[p] is harmless (cleared first)
            unsigned alive = (k == 32) ? 0xffffffffu : ((1u << k) - 1u);
            unsigned kept = 0;
            while (alive) {
                const int pbest = __ffs(alive) - 1;
                kept  |= (1u << pbest);
                alive &= ~(1u << pbest);
                alive &= ~Msm[warpId * 32 + pbest];                // broadcast LDS
            }
            if (lane < k && ((kept >> lane) & 1u)) skeep[bi] = 1;
            __syncwarp();
        } else if (lane == 0) {
            // rare fallback: serial selection-based greedy (32 < k <= 64)
            const unsigned long long* keys = &skey[c * MAXK];
            unsigned long long alive = (k >= 64) ? ~0ull : ((1ull << k) - 1ull);
            while (alive) {
                unsigned long long best = 0; int bs = 0;
                unsigned long long m = alive;
                while (m) {
                    const int j = __ffsll((long long)m) - 1;
                    m &= m - 1;
                    if (keys[j] > best) { best = keys[j]; bs = j; }
                }
                const int bib = (HW - 1) - (int)(best & (HW - 1));
                skeep[bib] = 1;
                alive &= ~(1ull << bs);

                const float4 cbb = sbox[bib];
                const float  ca = (cbb.z - cbb.x) * (cbb.w - cbb.y);
                m = alive;
                while (m) {
                    const int j = __ffsll((long long)m) - 1;
                    m &= m - 1;
                    const int bj = (HW - 1) - (int)(keys[j] & (HW - 1));
                    const float4 kb = sbox[bj];
                    float iw = fminf(cbb.z, kb.z) - fmaxf(cbb.x, kb.x);
                    iw = fmaxf(iw, 0.0f);
                    float ih = fminf(cbb.w, kb.w) - fmaxf(cbb.y, kb.y);
                    ih = fmaxf(ih, 0.0f);
                    const float inter = iw * ih;
                    const float kba = (kb.z - kb.x) * (kb.w - kb.y);
                    const float iou = inter / (ca + kba - inter + 1e-9f);
                    if (iou > NMS_TH) alive &= ~(1ull << j);
                }
            }
        }
    }
    __syncthreads();

    // ---------------- Phase 4: keep writeout ----------------
    out[BBOX_ELEMS + (size_t)n * HW + t] = (float)skeep[t];
}

extern "C" void kernel_launch(void* const* d_in, const int* in_sizes, int n_in,
                              void* d_out, int out_size)
{
    (void)in_sizes; (void)n_in; (void)out_size;
    const float* preds = (const float*)d_in[0];
    float* out = (float*)d_out;
    static int attr_set = 0;
    if (!attr_set) {
        cudaFuncSetAttribute(fastestdet_fused_kernel,
                             cudaFuncAttributeMaxDynamicSharedMemorySize, SMEM_TOTAL);
        attr_set = 1;
    }
    fastestdet_fused_kernel<<<N_IMG, 1024, SMEM_TOTAL>>>(preds, out);
}

// round 8
// speedup vs baseline: 1.2112x; 1.2112x over previous
#include <cuda_runtime.h>
#include <math.h>

#define N_IMG   64
#define C_PRED  85
#define HDIM    32
#define HW      1024
#define NCLS    80
#define CONF_TH 0.25f
#define NMS_TH  0.35f
#define MAXK    64          // per-class candidate cap (mean ~6 for this data)

// Output layout (float32): [ bboxes: N*HW*6 ][ keep: N*HW ]
#define BBOX_ELEMS ((size_t)N_IMG * HW * 6)

// Scratch (allocation-free __device__ globals; zero-initialized at load)
__device__ int                g_cnt [N_IMG * NCLS];
__device__ unsigned long long g_key [N_IMG * NCLS * MAXK];
__device__ float4             g_cbox[N_IMG * NCLS * MAXK];

// ================= Kernel 1: decode + class bucketing (full chip) =================
__global__ __launch_bounds__(128)
void decode_kernel(const float* __restrict__ preds, float* __restrict__ out)
{
    const int n = blockIdx.y;                          // image
    const int t = blockIdx.x * 128 + threadIdx.x;      // cell 0..1023

    const float* p = preds + (size_t)n * C_PRED * HW + t;

    const float pobj = p[0];
    const float r0 = p[1 * HW];
    const float r1 = p[2 * HW];
    const float r2 = p[3 * HW];
    const float r3 = p[4 * HW];

    float mx = p[5 * HW];
    int   am = 0;
    #pragma unroll 8
    for (int c = 1; c < NCLS; ++c) {
        float v = p[(5 + c) * HW];
        if (v > mx) { mx = v; am = c; }   // strict '>' => first max index (jnp.argmax)
    }
    const float score = pobj * mx;

    const int w = t & (HDIM - 1);
    const int h = t >> 5;

    const float bw  = 1.0f / (1.0f + expf(-r2));
    const float bh  = 1.0f / (1.0f + expf(-r3));
    const float bcx = (tanhf(r0) + (float)w) * (1.0f / 32.0f);  // /32 exact
    const float bcy = (tanhf(r1) + (float)h) * (1.0f / 32.0f);

    const float x1 = bcx - 0.5f * bw;
    const float y1 = bcy - 0.5f * bh;
    const float x2 = bcx + 0.5f * bw;
    const float y2 = bcy + 0.5f * bh;

    // bboxes to output
    float* ob = out + ((size_t)n * HW + t) * 6;
    ob[0] = x1; ob[1] = y1; ob[2] = x2; ob[3] = y2;
    ob[4] = score; ob[5] = (float)am;

    // zero-fill keep mask (NMS kernel scatter-writes the 1s)
    out[BBOX_ELEMS + (size_t)n * HW + t] = 0.0f;

    // bucket valid boxes by (image, class)
    if (score > CONF_TH) {
        const int cid  = n * NCLS + am;
        const int slot = atomicAdd(&g_cnt[cid], 1);
        if (slot < MAXK) {
            const unsigned long long kb = (unsigned long long)__float_as_uint(score);
            g_key [cid * MAXK + slot] = (kb << 10) | (unsigned long long)(HW - 1 - t);
            g_cbox[cid * MAXK + slot] = make_float4(x1, y1, x2, y2);
        }
    }
}

// ================= Kernel 2: warp per (image,class), matrix greedy =================
#define NWARPS 8
__global__ __launch_bounds__(32 * NWARPS)
void nms_kernel(float* __restrict__ out)
{
    __shared__ unsigned long long srtkey[NWARPS * 32];
    __shared__ float4             srtbox[NWARPS * 32];
    __shared__ unsigned           Msm   [NWARPS * 32];

    const int lane = threadIdx.x & 31;
    const int wId  = threadIdx.x >> 5;
    const int cInImg = blockIdx.x * NWARPS + wId;      // 0..79
    const int n   = blockIdx.y;
    const int cid = n * NCLS + cInImg;

    int k = 0;
    if (lane == 0) k = g_cnt[cid];
    k = __shfl_sync(0xffffffffu, k, 0);
    if (k > MAXK) k = MAXK;

    float* keep = out + BBOX_ELEMS + (size_t)n * HW;

    if (k > 0 && k <= 32) {
        // parallel load of keys + boxes (slot order arbitrary)
        unsigned long long key = 0;
        float4 box = make_float4(0.f, 0.f, 0.f, 0.f);
        if (lane < k) {
            key = g_key [cid * MAXK + lane];
            box = g_cbox[cid * MAXK + lane];
        }

        // rank = #{keys strictly greater}  (stable argsort(-score); keys distinct)
        int rank = 0;
        #pragma unroll 4
        for (int j = 0; j < k; ++j) {
            const unsigned long long kj = __shfl_sync(0xffffffffu, key, j);
            if (lane < k && kj > key) ++rank;
        }

        // permute to lane == rank via smem
        if (lane < k) {
            srtkey[wId * 32 + rank] = key;
            srtbox[wId * 32 + rank] = box;
        }
        __syncwarp();

        int    bi = 0;
        float4 cb = make_float4(0.f, 0.f, 0.f, 0.f);
        float  area = 0.f;
        if (lane < k) {
            cb   = srtbox[wId * 32 + lane];
            bi   = (HW - 1) - (int)(srtkey[wId * 32 + lane] & (HW - 1));
            area = (cb.z - cb.x) * (cb.w - cb.y);
        }

        // suppression row: bit j set if IoU(me, box_j) > th (IoU symmetric)
        unsigned M = 0;
        if (lane < k) {
            for (int j = 0; j < k; ++j) {
                const float4 kb = srtbox[wId * 32 + j];        // broadcast LDS128
                float iw = fminf(cb.z, kb.z) - fmaxf(cb.x, kb.x);
                iw = fmaxf(iw, 0.0f);
                float ih = fminf(cb.w, kb.w) - fmaxf(cb.y, kb.y);
                ih = fmaxf(ih, 0.0f);
                const float inter = iw * ih;
                const float kba = (kb.z - kb.x) * (kb.w - kb.y);
                const float iou = inter / (area + kba - inter + 1e-9f);
                if (iou > NMS_TH) M |= (1u << j);
            }
            Msm[wId * 32 + lane] = M;
        }
        __syncwarp();

        // uniform scalar greedy (self-bit in M[p] harmless: cleared first)
        unsigned alive = (k == 32) ? 0xffffffffu : ((1u << k) - 1u);
        unsigned kept = 0;
        while (alive) {
            const int pb = __ffs(alive) - 1;
            kept  |= (1u << pb);
            alive &= ~(1u << pb);
            alive &= ~Msm[wId * 32 + pb];                      // broadcast LDS
        }
        if (lane < k && ((kept >> lane) & 1u)) keep[bi] = 1.0f;
    } else if (k > 32 && lane == 0) {
        // rare fallback: serial selection-based greedy (32 < k <= 64)
        const unsigned long long* keys = &g_key [cid * MAXK];
        const float4*             boxs = &g_cbox[cid * MAXK];
        unsigned long long alive = (k >= 64) ? ~0ull : ((1ull << k) - 1ull);
        while (alive) {
            unsigned long long best = 0; int bs = 0;
            unsigned long long m = alive;
            while (m) {
                const int j = __ffsll((long long)m) - 1;
                m &= m - 1;
                if (keys[j] > best) { best = keys[j]; bs = j; }
            }
            const int bib = (HW - 1) - (int)(best & (HW - 1));
            keep[bib] = 1.0f;
            alive &= ~(1ull << bs);

            const float4 cbb = boxs[bs];
            const float  ca = (cbb.z - cbb.x) * (cbb.w - cbb.y);
            m = alive;
            while (m) {
                const int j = __ffsll((long long)m) - 1;
                m &= m - 1;
                const float4 kb = boxs[j];
                float iw = fminf(cbb.z, kb.z) - fmaxf(cbb.x, kb.x);
                iw = fmaxf(iw, 0.0f);
                float ih = fminf(cbb.w, kb.w) - fmaxf(cbb.y, kb.y);
                ih = fmaxf(ih, 0.0f);
                const float inter = iw * ih;
                const float kba = (kb.z - kb.x) * (kb.w - kb.y);
                const float iou = inter / (ca + kba - inter + 1e-9f);
                if (iou > NMS_TH) alive &= ~(1ull << j);
            }
        }
    }

    // reset counter for the next graph replay (this warp owns cid)
    if (lane == 0) g_cnt[cid] = 0;
}

extern "C" void kernel_launch(void* const* d_in, const int* in_sizes, int n_in,
                              void* d_out, int out_size)
{
    (void)in_sizes; (void)n_in; (void)out_size;
    const float* preds = (const float*)d_in[0];
    float* out = (float*)d_out;
    decode_kernel<<<dim3(HW / 128, N_IMG), 128>>>(preds, out);
    nms_kernel<<<dim3(NCLS / NWARPS, N_IMG), 32 * NWARPS>>>(out);
}